// round 1
// baseline (speedup 1.0000x reference)
#include <cuda_runtime.h>
#include <cstdint>
#include <cstddef>

#define N_USERC 100000
#define M_ITEMC 50000
#define N_NODEC 150000
#define DD      64
#define BSEED   2048
#define SNB     20
#define M1ROWS  (BSEED*SNB)          // 40960
#define MROWS   (BSEED*SNB + BSEED)  // 43008

// ---------------- device scratch (static globals; allocation-free) ----------
__device__ float g_x[(size_t)N_NODEC * DD];     // node embeddings
__device__ float g_m[(size_t)MROWS * DD];       // neighbor means (m2 then m1)
__device__ float g_agg[(size_t)MROWS * DD];     // means @ Wv0 + bv0
__device__ float g_h[(size_t)MROWS * DD];       // h1 (40960 rows) then h0 (2048)
__device__ float g_mh[(size_t)BSEED * DD];      // mean over h1 per seed
__device__ float g_agg1[(size_t)BSEED * DD];    // mh @ Wv1 + bv1

typedef unsigned long long ull;

__device__ __forceinline__ ull splat2(float a) {
    ull r; asm("mov.b64 %0, {%1, %1};" : "=l"(r) : "f"(a)); return r;
}
__device__ __forceinline__ void fma2(ull& acc, ull a, ull b) {
    asm("fma.rn.f32x2 %0, %1, %2, %0;" : "+l"(acc) : "l"(a), "l"(b));
}
__device__ __forceinline__ float2 unpack2(ull v) {
    float2 r; asm("mov.b64 {%0, %1}, %2;" : "=f"(r.x), "=f"(r.y) : "l"(v)); return r;
}

struct Frag { ull c[4][2]; };

__device__ __forceinline__ void frag_zero(Frag& f) {
#pragma unroll
    for (int i = 0; i < 4; i++) { f.c[i][0] = 0ull; f.c[i][1] = 0ull; }
}

// As: [64][17] (row = node-local, col = kk, +1 pad), Bs: [16][64]
__device__ __forceinline__ void mma_tile(Frag& f, const float* As, const float* Bs,
                                         int ty, int tx) {
#pragma unroll
    for (int kk = 0; kk < 16; ++kk) {
        const ulonglong2 b = *reinterpret_cast<const ulonglong2*>(Bs + kk * 64 + tx * 4);
#pragma unroll
        for (int i = 0; i < 4; i++) {
            float a = As[(ty * 4 + i) * 17 + kk];
            ull s = splat2(a);
            fma2(f.c[i][0], s, b.x);
            fma2(f.c[i][1], s, b.y);
        }
    }
}

// =================== stage 1: user node embeddings ==========================
// feature layout (K): [0,64) id | [64,128) feat-bag mean | [128,224) text (3x32)
//                     [224,524) word300 | [524,534) numeric | pad to 544
__global__ void __launch_bounds__(256) user_x_kernel(
    const int* __restrict__ feat_idx, const int* __restrict__ text_idx,
    const float* __restrict__ id_emb, const float* __restrict__ feat_emb,
    const float* __restrict__ word_emb, const float* __restrict__ w300,
    const float* __restrict__ numer,
    const float* __restrict__ Wproj, const float* __restrict__ Wnum,
    const float* __restrict__ bproj, const float* __restrict__ bnum)
{
    __shared__ __align__(16) float As[64 * 17];
    __shared__ __align__(16) float Bs[16 * 64];
    __shared__ int   sfi[64 * 10];
    __shared__ int   sti[64 * 24];
    __shared__ float sbias[64];

    const int tid = threadIdx.x;
    const int m0 = blockIdx.x * 64;
    const int tx = tid & 15, ty = tid >> 4;

    for (int i = tid; i < 64 * 10; i += 256) {
        int ln = i / 10, node = m0 + ln;
        sfi[i] = (node < N_USERC) ? feat_idx[node * 10 + (i - ln * 10)] : 0;
    }
    for (int i = tid; i < 64 * 24; i += 256) {
        int ln = i / 24, node = m0 + ln;
        sti[i] = (node < N_USERC) ? text_idx[node * 24 + (i - ln * 24)] : 0;
    }
    if (tid < 64) sbias[tid] = bproj[tid] + bnum[tid];

    Frag f; frag_zero(f);

    for (int k0 = 0; k0 < 544; k0 += 16) {
        __syncthreads();
        // B tile: splice Wproj rows [0,524), Wnum rows [524,534), zeros beyond
        for (int i = tid; i < 16 * 64; i += 256) {
            int kk = i >> 6, n = i & 63, r = k0 + kk;
            float v = 0.f;
            if (r < 524) v = Wproj[r * 64 + n];
            else if (r < 534) v = Wnum[(r - 524) * 64 + n];
            Bs[i] = v;
        }
        // A tile assembly (consecutive threads -> consecutive cols: coalesced)
        for (int i = tid; i < 64 * 16; i += 256) {
            int ln = i >> 4, kk = i & 15;
            int node = m0 + ln;
            int col = k0 + kk;
            float v = 0.f;
            if (node < N_USERC) {
                if (col < 64) {
                    v = __ldg(id_emb + (size_t)node * 64 + col);
                } else if (col < 128) {
                    int c = col - 64; float s = 0.f;
#pragma unroll
                    for (int j = 0; j < 10; j++)
                        s += __ldg(feat_emb + (size_t)sfi[ln * 10 + j] * 64 + c);
                    v = s * 0.1f;
                } else if (col < 224) {
                    int q = col - 128; int so = (q >> 5) * 8; int c = q & 31; float s = 0.f;
#pragma unroll
                    for (int t = 0; t < 8; t++)
                        s += __ldg(word_emb + (size_t)sti[ln * 24 + so + t] * 32 + c);
                    v = s * 0.125f;
                } else if (col < 524) {
                    v = __ldg(w300 + (size_t)node * 300 + (col - 224));
                } else if (col < 534) {
                    v = __ldg(numer + (size_t)node * 10 + (col - 524));
                }
            }
            As[ln * 17 + kk] = v;
        }
        __syncthreads();
        mma_tile(f, As, Bs, ty, tx);
    }

    const int col0 = tx * 4;
#pragma unroll
    for (int i = 0; i < 4; i++) {
        int node = m0 + ty * 4 + i;
        if (node < N_USERC) {
            float2 lo = unpack2(f.c[i][0]);
            float2 hi = unpack2(f.c[i][1]);
            float4 o;
            o.x = lo.x + sbias[col0 + 0];
            o.y = lo.y + sbias[col0 + 1];
            o.z = hi.x + sbias[col0 + 2];
            o.w = hi.y + sbias[col0 + 3];
            *reinterpret_cast<float4*>(g_x + (size_t)node * 64 + col0) = o;
        }
    }
}

// =================== stage 1: item node embeddings ==========================
// K layout: [0,64) id | [64,128) feat | [128,224) text | [224,524) word300
//           [524,1292) sent768 | [1292,1302) numeric | pad to 1312
__global__ void __launch_bounds__(256) item_x_kernel(
    const int* __restrict__ feat_idx, const int* __restrict__ text_idx,
    const float* __restrict__ id_emb, const float* __restrict__ feat_emb,
    const float* __restrict__ word_emb, const float* __restrict__ w300,
    const float* __restrict__ s768, const float* __restrict__ numer,
    const float* __restrict__ Wproj, const float* __restrict__ Wnum,
    const float* __restrict__ bproj, const float* __restrict__ bnum)
{
    __shared__ __align__(16) float As[64 * 17];
    __shared__ __align__(16) float Bs[16 * 64];
    __shared__ int   sfi[64 * 10];
    __shared__ int   sti[64 * 24];
    __shared__ float sbias[64];

    const int tid = threadIdx.x;
    const int m0 = blockIdx.x * 64;
    const int tx = tid & 15, ty = tid >> 4;

    for (int i = tid; i < 64 * 10; i += 256) {
        int ln = i / 10, node = m0 + ln;
        sfi[i] = (node < M_ITEMC) ? feat_idx[node * 10 + (i - ln * 10)] : 0;
    }
    for (int i = tid; i < 64 * 24; i += 256) {
        int ln = i / 24, node = m0 + ln;
        sti[i] = (node < M_ITEMC) ? text_idx[node * 24 + (i - ln * 24)] : 0;
    }
    if (tid < 64) sbias[tid] = bproj[tid] + bnum[tid];

    Frag f; frag_zero(f);

    for (int k0 = 0; k0 < 1312; k0 += 16) {
        __syncthreads();
        for (int i = tid; i < 16 * 64; i += 256) {
            int kk = i >> 6, n = i & 63, r = k0 + kk;
            float v = 0.f;
            if (r < 1292) v = Wproj[r * 64 + n];
            else if (r < 1302) v = Wnum[(r - 1292) * 64 + n];
            Bs[i] = v;
        }
        for (int i = tid; i < 64 * 16; i += 256) {
            int ln = i >> 4, kk = i & 15;
            int node = m0 + ln;
            int col = k0 + kk;
            float v = 0.f;
            if (node < M_ITEMC) {
                if (col < 64) {
                    v = __ldg(id_emb + (size_t)node * 64 + col);
                } else if (col < 128) {
                    int c = col - 64; float s = 0.f;
#pragma unroll
                    for (int j = 0; j < 10; j++)
                        s += __ldg(feat_emb + (size_t)sfi[ln * 10 + j] * 64 + c);
                    v = s * 0.1f;
                } else if (col < 224) {
                    int q = col - 128; int so = (q >> 5) * 8; int c = q & 31; float s = 0.f;
#pragma unroll
                    for (int t = 0; t < 8; t++)
                        s += __ldg(word_emb + (size_t)sti[ln * 24 + so + t] * 32 + c);
                    v = s * 0.125f;
                } else if (col < 524) {
                    v = __ldg(w300 + (size_t)node * 300 + (col - 224));
                } else if (col < 1292) {
                    v = __ldg(s768 + (size_t)node * 768 + (col - 524));
                } else if (col < 1302) {
                    v = __ldg(numer + (size_t)node * 10 + (col - 1292));
                }
            }
            As[ln * 17 + kk] = v;
        }
        __syncthreads();
        mma_tile(f, As, Bs, ty, tx);
    }

    const int col0 = tx * 4;
#pragma unroll
    for (int i = 0; i < 4; i++) {
        int node = m0 + ty * 4 + i;
        if (node < M_ITEMC) {
            float2 lo = unpack2(f.c[i][0]);
            float2 hi = unpack2(f.c[i][1]);
            float4 o;
            o.x = lo.x + sbias[col0 + 0];
            o.y = lo.y + sbias[col0 + 1];
            o.z = hi.x + sbias[col0 + 2];
            o.w = hi.y + sbias[col0 + 3];
            *reinterpret_cast<float4*>(g_x + (size_t)(N_USERC + node) * 64 + col0) = o;
        }
    }
}

// =================== stage 2: neighbor means ================================
// row < 40960: m2[b*S+s] = mean_k x[neigh2[b,s,k]]
// row >= 40960: m1[b]    = mean_s x[neigh1[b,s]]
__global__ void mean_kernel(const int* __restrict__ neigh2, const int* __restrict__ neigh1)
{
    int gw = (blockIdx.x * blockDim.x + threadIdx.x) >> 5;
    int lane = threadIdx.x & 31;
    if (gw >= MROWS) return;
    const int* idx = (gw < M1ROWS) ? (neigh2 + (size_t)gw * SNB)
                                   : (neigh1 + (size_t)(gw - M1ROWS) * SNB);
    float2 acc = make_float2(0.f, 0.f);
#pragma unroll
    for (int j = 0; j < SNB; j++) {
        int n = __ldg(idx + j);
        float2 v = *reinterpret_cast<const float2*>(g_x + (size_t)n * 64 + lane * 2);
        acc.x += v.x; acc.y += v.y;
    }
    acc.x *= 0.05f; acc.y *= 0.05f;
    *reinterpret_cast<float2*>(g_m + (size_t)gw * 64 + lane * 2) = acc;
}

// mean over h1 per seed: g_mh[b] = mean_s g_h[b*S+s]
__global__ void meanh_kernel()
{
    int gw = (blockIdx.x * blockDim.x + threadIdx.x) >> 5;
    int lane = threadIdx.x & 31;
    if (gw >= BSEED) return;
    float2 acc = make_float2(0.f, 0.f);
#pragma unroll
    for (int j = 0; j < SNB; j++) {
        float2 v = *reinterpret_cast<const float2*>(g_h + (size_t)(gw * SNB + j) * 64 + lane * 2);
        acc.x += v.x; acc.y += v.y;
    }
    acc.x *= 0.05f; acc.y *= 0.05f;
    *reinterpret_cast<float2*>(g_mh + (size_t)gw * 64 + lane * 2) = acc;
}

// =================== stage 2: plain GEMM [M,64]@[64,64] + bias ==============
__global__ void __launch_bounds__(256) gemm64_kernel(
    const float* __restrict__ A, const float* __restrict__ W,
    const float* __restrict__ bias, float* __restrict__ out, int M)
{
    __shared__ __align__(16) float As[64 * 17];
    __shared__ __align__(16) float Bs[16 * 64];
    __shared__ float sbias[64];

    const int tid = threadIdx.x;
    const int m0 = blockIdx.x * 64;
    const int tx = tid & 15, ty = tid >> 4;
    if (tid < 64) sbias[tid] = bias[tid];

    Frag f; frag_zero(f);
    for (int k0 = 0; k0 < 64; k0 += 16) {
        __syncthreads();
        for (int i = tid; i < 16 * 64; i += 256) {
            int kk = i >> 6, n = i & 63;
            Bs[i] = W[(k0 + kk) * 64 + n];
        }
        for (int i = tid; i < 64 * 16; i += 256) {
            int ln = i >> 4, kk = i & 15;
            int r = m0 + ln;
            As[ln * 17 + kk] = (r < M) ? __ldg(A + (size_t)r * 64 + k0 + kk) : 0.f;
        }
        __syncthreads();
        mma_tile(f, As, Bs, ty, tx);
    }

    const int col0 = tx * 4;
#pragma unroll
    for (int i = 0; i < 4; i++) {
        int r = m0 + ty * 4 + i;
        if (r < M) {
            float2 lo = unpack2(f.c[i][0]);
            float2 hi = unpack2(f.c[i][1]);
            float4 o;
            o.x = lo.x + sbias[col0 + 0];
            o.y = lo.y + sbias[col0 + 1];
            o.z = hi.x + sbias[col0 + 2];
            o.w = hi.y + sbias[col0 + 3];
            *reinterpret_cast<float4*>(out + (size_t)r * 64 + col0) = o;
        }
    }
}

// ============ stage 2: SAGE concat GEMM [self | agg] @ [128,64] =============
// mode 0: self = g_x[neigh1[r]] (r<40960) or g_x[seeds[r-40960]]  (layer 0)
// mode 1: self = left[r]                                          (layer 1)
__global__ void __launch_bounds__(256) sage_kernel(
    const int* __restrict__ neigh1, const int* __restrict__ seeds,
    const float* __restrict__ left, const float* __restrict__ right,
    const float* __restrict__ W, const float* __restrict__ bias,
    float* __restrict__ out, int M, int mode, int do_relu)
{
    __shared__ __align__(16) float As[64 * 17];
    __shared__ __align__(16) float Bs[16 * 64];
    __shared__ float sbias[64];
    __shared__ int   ssel[64];

    const int tid = threadIdx.x;
    const int m0 = blockIdx.x * 64;
    const int tx = tid & 15, ty = tid >> 4;

    if (tid < 64) {
        int r = m0 + tid;
        int n = 0;
        if (mode == 0 && r < M)
            n = (r < M1ROWS) ? neigh1[r] : seeds[r - M1ROWS];
        ssel[tid] = n;
        sbias[tid] = bias[tid];
    }

    Frag f; frag_zero(f);
    for (int k0 = 0; k0 < 128; k0 += 16) {
        __syncthreads();
        for (int i = tid; i < 16 * 64; i += 256) {
            int kk = i >> 6, n = i & 63;
            Bs[i] = W[(k0 + kk) * 64 + n];
        }
        for (int i = tid; i < 64 * 16; i += 256) {
            int ln = i >> 4, kk = i & 15;
            int r = m0 + ln;
            int col = k0 + kk;
            float v = 0.f;
            if (r < M) {
                if (col < 64) {
                    if (mode == 0) v = __ldg(left + (size_t)ssel[ln] * 64 + col);
                    else           v = __ldg(left + (size_t)r * 64 + col);
                } else {
                    v = __ldg(right + (size_t)r * 64 + (col - 64));
                }
            }
            As[ln * 17 + kk] = v;
        }
        __syncthreads();
        mma_tile(f, As, Bs, ty, tx);
    }

    const int col0 = tx * 4;
#pragma unroll
    for (int i = 0; i < 4; i++) {
        int r = m0 + ty * 4 + i;
        if (r < M) {
            float2 lo = unpack2(f.c[i][0]);
            float2 hi = unpack2(f.c[i][1]);
            float4 o;
            o.x = lo.x + sbias[col0 + 0];
            o.y = lo.y + sbias[col0 + 1];
            o.z = hi.x + sbias[col0 + 2];
            o.w = hi.y + sbias[col0 + 3];
            if (do_relu) {
                o.x = fmaxf(o.x, 0.f); o.y = fmaxf(o.y, 0.f);
                o.z = fmaxf(o.z, 0.f); o.w = fmaxf(o.w, 0.f);
            }
            *reinterpret_cast<float4*>(out + (size_t)r * 64 + col0) = o;
        }
    }
}

// ============================ launch =========================================
extern "C" void kernel_launch(void* const* d_in, const int* in_sizes, int n_in,
                              void* d_out, int out_size)
{
    const int*   seeds  = (const int*)d_in[0];
    const int*   neigh1 = (const int*)d_in[1];
    const int*   neigh2 = (const int*)d_in[2];
    const int*   ufi    = (const int*)d_in[3];
    const int*   ifi    = (const int*)d_in[4];
    const int*   uti    = (const int*)d_in[5];
    const int*   iti    = (const int*)d_in[6];
    const float* uide   = (const float*)d_in[7];
    const float* iide   = (const float*)d_in[8];
    const float* ufe    = (const float*)d_in[9];
    const float* ife    = (const float*)d_in[10];
    const float* wemb   = (const float*)d_in[11];
    const float* uw300  = (const float*)d_in[12];
    const float* iw300  = (const float*)d_in[13];
    const float* is768  = (const float*)d_in[14];
    const float* unum   = (const float*)d_in[15];
    const float* inum   = (const float*)d_in[16];
    const float* Wnu    = (const float*)d_in[17];
    const float* bnu    = (const float*)d_in[18];
    const float* Wni    = (const float*)d_in[19];
    const float* bni    = (const float*)d_in[20];
    const float* Wpu    = (const float*)d_in[21];
    const float* bpu    = (const float*)d_in[22];
    const float* Wpi    = (const float*)d_in[23];
    const float* bpi    = (const float*)d_in[24];
    const float* Ww     = (const float*)d_in[25];
    const float* bw     = (const float*)d_in[26];
    const float* Wv     = (const float*)d_in[27];
    const float* bv     = (const float*)d_in[28];
    float* out = (float*)d_out;

    float *pm, *pagg, *ph, *pmh, *pagg1, *px;
    cudaGetSymbolAddress((void**)&px,    g_x);
    cudaGetSymbolAddress((void**)&pm,    g_m);
    cudaGetSymbolAddress((void**)&pagg,  g_agg);
    cudaGetSymbolAddress((void**)&ph,    g_h);
    cudaGetSymbolAddress((void**)&pmh,   g_mh);
    cudaGetSymbolAddress((void**)&pagg1, g_agg1);

    // Stage 1: node embeddings for all nodes
    user_x_kernel<<<(N_USERC + 63) / 64, 256>>>(ufi, uti, uide, ufe, wemb, uw300,
                                                unum, Wpu, Wnu, bpu, bnu);
    item_x_kernel<<<(M_ITEMC + 63) / 64, 256>>>(ifi, iti, iide, ife, wemb, iw300,
                                                is768, inum, Wpi, Wni, bpi, bni);

    // Stage 2: neighbor means (linear-layer commutes with mean)
    mean_kernel<<<(MROWS * 32 + 255) / 256, 256>>>(neigh2, neigh1);

    // agg = mean @ Wv0 + bv0
    gemm64_kernel<<<(MROWS + 63) / 64, 256>>>(pm, Wv, bv, pagg, MROWS);

    // layer 0: h = relu([self, agg] @ Ww0 + bw0)  (h1 rows then h0 rows)
    sage_kernel<<<(MROWS + 63) / 64, 256>>>(neigh1, seeds, px, pagg, Ww, bw,
                                            ph, MROWS, 0, 1);

    // mean over h1 per seed
    meanh_kernel<<<(BSEED * 32 + 255) / 256, 256>>>();

    // agg1 = mh @ Wv1 + bv1
    gemm64_kernel<<<(BSEED + 63) / 64, 256>>>(pmh, Wv + 64 * 64, bv + 64, pagg1, BSEED);

    // layer 1: out = [h0, agg1] @ Ww1 + bw1 (no relu)
    sage_kernel<<<(BSEED + 63) / 64, 256>>>(nullptr, nullptr,
                                            ph + (size_t)M1ROWS * 64, pagg1,
                                            Ww + 128 * 64, bw + 64,
                                            out, BSEED, 1, 0);
}

// round 2
// speedup vs baseline: 1.3536x; 1.3536x over previous
#include <cuda_runtime.h>
#include <cstdint>
#include <cstddef>

#define N_USERC 100000
#define M_ITEMC 50000
#define N_NODEC 150000
#define DD      64
#define BSEED   2048
#define SNB     20
#define M1ROWS  (BSEED*SNB)          // 40960
#define MROWS   (BSEED*SNB + BSEED)  // 43008

// ---------------- device scratch (static globals; allocation-free) ----------
__device__ float g_x[(size_t)N_NODEC * DD];     // node embeddings
__device__ float g_m[(size_t)MROWS * DD];       // neighbor means
__device__ float g_agg[(size_t)MROWS * DD];     // means @ Wv0 + bv0
__device__ float g_h[(size_t)MROWS * DD];       // h1 then h0
__device__ float g_mh[(size_t)BSEED * DD];      // mean over h1 per seed
__device__ float g_agg1[(size_t)BSEED * DD];    // mh @ Wv1 + bv1

__device__ __forceinline__ uint32_t f2tf(float v) {
    uint32_t r; asm("cvt.rna.tf32.f32 %0, %1;" : "=r"(r) : "f"(v)); return r;
}

__device__ __forceinline__ void mma_tf32(float c[4],
    uint32_t a0, uint32_t a1, uint32_t a2, uint32_t a3,
    uint32_t b0, uint32_t b1)
{
    asm volatile(
        "mma.sync.aligned.m16n8k8.row.col.f32.tf32.tf32.f32 "
        "{%0,%1,%2,%3},{%4,%5,%6,%7},{%8,%9},{%0,%1,%2,%3};"
        : "+f"(c[0]), "+f"(c[1]), "+f"(c[2]), "+f"(c[3])
        : "r"(a0), "r"(a1), "r"(a2), "r"(a3), "r"(b0), "r"(b1));
}

struct Args {
    const int*   fi;      // feat idx  [nodes*10]
    const int*   ti;      // text idx  [nodes*24]
    const int*   neigh1;  // for sage l0 self-select
    const int*   seeds;
    const float* id_emb;
    const float* feat_emb;
    const float* word_emb;
    const float* w300;
    const float* s768;
    const float* numer;
    const float* A;       // plain A (mode 2) / left (mode 4)
    const float* right;   // agg part (modes 3,4)
    const float* W;       // Wproj or layer weight [K x 64]
    const float* Wnum;    // numeric weight (modes 0,1)
    const float* bias;
    const float* bnum;
    float*       out;
    int M, K, relu, wsplit; // wsplit: rows of W before switching to Wnum
};

// MODE: 0 user proj, 1 item proj, 2 plain [M,K]@[K,64], 3 sage-l0, 4 sage-l1
template<int MODE>
__global__ void __launch_bounds__(256) mma_fused_kernel(Args p)
{
    __shared__ uint32_t As[128][20];   // [m][k], pad 20 -> conflict-free frags
    __shared__ uint32_t Bs[16][72];    // [k][n], pad 72
    __shared__ float    sbias[64];
    __shared__ int      sfi[128 * 10];
    __shared__ int      sti[128 * 24];
    __shared__ int      ssel[128];

    const int tid  = threadIdx.x;
    const int lane = tid & 31;
    const int wid  = tid >> 5;
    const int wm   = wid >> 1;        // 0..3
    const int wn   = wid & 1;         // 0..1
    const int m0   = blockIdx.x * 128;

    if (tid < 64) {
        float b = p.bias[tid];
        if (MODE == 0 || MODE == 1) b += p.bnum[tid];
        sbias[tid] = b;
    }

    if (MODE == 0 || MODE == 1) {
        const int bound = (MODE == 0) ? N_USERC : M_ITEMC;
        for (int i = tid; i < 128 * 10; i += 256) {
            int ln = i / 10, node = m0 + ln;
            sfi[i] = (node < bound) ? p.fi[node * 10 + (i - ln * 10)] : 0;
        }
        for (int i = tid; i < 128 * 24; i += 256) {
            int ln = i / 24, node = m0 + ln;
            sti[i] = (node < bound) ? p.ti[node * 24 + (i - ln * 24)] : 0;
        }
    }
    if (MODE == 3) {
        if (tid < 128) {
            int r = m0 + tid;
            int n = 0;
            if (r < p.M) n = (r < M1ROWS) ? p.neigh1[r] : p.seeds[r - M1ROWS];
            ssel[tid] = n;
        }
    }

    float c[2][4][4];
#pragma unroll
    for (int a = 0; a < 2; a++)
#pragma unroll
        for (int b = 0; b < 4; b++)
#pragma unroll
            for (int d = 0; d < 4; d++) c[a][b][d] = 0.f;

    for (int k0 = 0; k0 < p.K; k0 += 16) {
        __syncthreads();
        // ---- B tile ----
        for (int i = tid; i < 16 * 64; i += 256) {
            int kk = i >> 6, n = i & 63, r = k0 + kk;
            float v = 0.f;
            if (MODE == 0 || MODE == 1) {
                if (r < p.wsplit)            v = p.W[(size_t)r * 64 + n];
                else if (r < p.wsplit + 10)  v = p.Wnum[(size_t)(r - p.wsplit) * 64 + n];
            } else {
                if (r < p.K) v = p.W[(size_t)r * 64 + n];
            }
            Bs[kk][n] = f2tf(v);
        }
        // ---- A tile (gather-assembled) ----
        for (int i = tid; i < 128 * 16; i += 256) {
            int ln = i >> 4, kk = i & 15;
            int r = m0 + ln;
            int col = k0 + kk;
            float v = 0.f;
            if (MODE == 0 || MODE == 1) {
                const int bound = (MODE == 0) ? N_USERC : M_ITEMC;
                if (r < bound) {
                    if (col < 64) {
                        v = __ldg(p.id_emb + (size_t)r * 64 + col);
                    } else if (col < 128) {
                        int cc = col - 64; float s = 0.f;
#pragma unroll
                        for (int j = 0; j < 10; j++)
                            s += __ldg(p.feat_emb + (size_t)sfi[ln * 10 + j] * 64 + cc);
                        v = s * 0.1f;
                    } else if (col < 224) {
                        int q = col - 128; int so = (q >> 5) * 8; int cc = q & 31;
                        float s = 0.f;
#pragma unroll
                        for (int t = 0; t < 8; t++)
                            s += __ldg(p.word_emb + (size_t)sti[ln * 24 + so + t] * 32 + cc);
                        v = s * 0.125f;
                    } else if (col < 524) {
                        v = __ldg(p.w300 + (size_t)r * 300 + (col - 224));
                    } else if (MODE == 1 && col < 1292) {
                        v = __ldg(p.s768 + (size_t)r * 768 + (col - 524));
                    } else {
                        int nbase = (MODE == 0) ? 524 : 1292;
                        if (col >= nbase && col < nbase + 10)
                            v = __ldg(p.numer + (size_t)r * 10 + (col - nbase));
                    }
                }
            } else if (MODE == 2) {
                if (r < p.M) v = __ldg(p.A + (size_t)r * 64 + col);
            } else if (MODE == 3) {
                if (r < p.M) {
                    if (col < 64) v = __ldg(g_x + (size_t)ssel[ln] * 64 + col);
                    else          v = __ldg(p.right + (size_t)r * 64 + (col - 64));
                }
            } else { // MODE 4
                if (r < p.M) {
                    if (col < 64) v = __ldg(p.A + (size_t)r * 64 + col);
                    else          v = __ldg(p.right + (size_t)r * 64 + (col - 64));
                }
            }
            As[ln][kk] = f2tf(v);
        }
        __syncthreads();

        // ---- compute ----
        const int r0 = lane >> 2, q = lane & 3;
#pragma unroll
        for (int ks = 0; ks < 2; ks++) {
            const int kb = ks * 8;
            uint32_t a[2][4], b[4][2];
#pragma unroll
            for (int mi = 0; mi < 2; mi++) {
                int mr = wm * 32 + mi * 16 + r0;
                a[mi][0] = As[mr][kb + q];
                a[mi][1] = As[mr + 8][kb + q];
                a[mi][2] = As[mr][kb + q + 4];
                a[mi][3] = As[mr + 8][kb + q + 4];
            }
#pragma unroll
            for (int ni = 0; ni < 4; ni++) {
                int nc = wn * 32 + ni * 8 + r0;
                b[ni][0] = Bs[kb + q][nc];
                b[ni][1] = Bs[kb + q + 4][nc];
            }
#pragma unroll
            for (int mi = 0; mi < 2; mi++)
#pragma unroll
                for (int ni = 0; ni < 4; ni++)
                    mma_tf32(c[mi][ni], a[mi][0], a[mi][1], a[mi][2], a[mi][3],
                             b[ni][0], b[ni][1]);
        }
    }

    // ---- epilogue ----
    const int r0 = lane >> 2, q = lane & 3;
#pragma unroll
    for (int mi = 0; mi < 2; mi++) {
#pragma unroll
        for (int ni = 0; ni < 4; ni++) {
            int col = wn * 32 + ni * 8 + 2 * q;
            float b0 = sbias[col], b1 = sbias[col + 1];
            int row = m0 + wm * 32 + mi * 16 + r0;
#pragma unroll
            for (int h = 0; h < 2; h++) {
                int rr = row + h * 8;
                if (rr < p.M) {
                    float v0 = c[mi][ni][h * 2 + 0] + b0;
                    float v1 = c[mi][ni][h * 2 + 1] + b1;
                    if (p.relu) { v0 = fmaxf(v0, 0.f); v1 = fmaxf(v1, 0.f); }
                    float2 o = make_float2(v0, v1);
                    *reinterpret_cast<float2*>(p.out + (size_t)rr * 64 + col) = o;
                }
            }
        }
    }
}

// =================== neighbor means ==========================================
__global__ void mean_kernel(const int* __restrict__ neigh2, const int* __restrict__ neigh1)
{
    int gw = (blockIdx.x * blockDim.x + threadIdx.x) >> 5;
    int lane = threadIdx.x & 31;
    if (gw >= MROWS) return;
    const int* idx = (gw < M1ROWS) ? (neigh2 + (size_t)gw * SNB)
                                   : (neigh1 + (size_t)(gw - M1ROWS) * SNB);
    float2 acc = make_float2(0.f, 0.f);
#pragma unroll
    for (int j = 0; j < SNB; j++) {
        int n = __ldg(idx + j);
        float2 v = *reinterpret_cast<const float2*>(g_x + (size_t)n * 64 + lane * 2);
        acc.x += v.x; acc.y += v.y;
    }
    acc.x *= 0.05f; acc.y *= 0.05f;
    *reinterpret_cast<float2*>(g_m + (size_t)gw * 64 + lane * 2) = acc;
}

__global__ void meanh_kernel()
{
    int gw = (blockIdx.x * blockDim.x + threadIdx.x) >> 5;
    int lane = threadIdx.x & 31;
    if (gw >= BSEED) return;
    float2 acc = make_float2(0.f, 0.f);
#pragma unroll
    for (int j = 0; j < SNB; j++) {
        float2 v = *reinterpret_cast<const float2*>(g_h + (size_t)(gw * SNB + j) * 64 + lane * 2);
        acc.x += v.x; acc.y += v.y;
    }
    acc.x *= 0.05f; acc.y *= 0.05f;
    *reinterpret_cast<float2*>(g_mh + (size_t)gw * 64 + lane * 2) = acc;
}

// ============================ launch =========================================
extern "C" void kernel_launch(void* const* d_in, const int* in_sizes, int n_in,
                              void* d_out, int out_size)
{
    const int*   seeds  = (const int*)d_in[0];
    const int*   neigh1 = (const int*)d_in[1];
    const int*   neigh2 = (const int*)d_in[2];
    const int*   ufi    = (const int*)d_in[3];
    const int*   ifi    = (const int*)d_in[4];
    const int*   uti    = (const int*)d_in[5];
    const int*   iti    = (const int*)d_in[6];
    const float* uide   = (const float*)d_in[7];
    const float* iide   = (const float*)d_in[8];
    const float* ufe    = (const float*)d_in[9];
    const float* ife    = (const float*)d_in[10];
    const float* wemb   = (const float*)d_in[11];
    const float* uw300  = (const float*)d_in[12];
    const float* iw300  = (const float*)d_in[13];
    const float* is768  = (const float*)d_in[14];
    const float* unum   = (const float*)d_in[15];
    const float* inum   = (const float*)d_in[16];
    const float* Wnu    = (const float*)d_in[17];
    const float* bnu    = (const float*)d_in[18];
    const float* Wni    = (const float*)d_in[19];
    const float* bni    = (const float*)d_in[20];
    const float* Wpu    = (const float*)d_in[21];
    const float* bpu    = (const float*)d_in[22];
    const float* Wpi    = (const float*)d_in[23];
    const float* bpi    = (const float*)d_in[24];
    const float* Ww     = (const float*)d_in[25];
    const float* bw     = (const float*)d_in[26];
    const float* Wv     = (const float*)d_in[27];
    const float* bv     = (const float*)d_in[28];
    float* out = (float*)d_out;

    float *pm, *pagg, *ph, *pmh, *pagg1, *px;
    cudaGetSymbolAddress((void**)&px,    g_x);
    cudaGetSymbolAddress((void**)&pm,    g_m);
    cudaGetSymbolAddress((void**)&pagg,  g_agg);
    cudaGetSymbolAddress((void**)&ph,    g_h);
    cudaGetSymbolAddress((void**)&pmh,   g_mh);
    cudaGetSymbolAddress((void**)&pagg1, g_agg1);

    Args p{};
    // ---- user projection: K padded 534->544 ----
    p.fi = ufi; p.ti = uti; p.id_emb = uide; p.feat_emb = ufe; p.word_emb = wemb;
    p.w300 = uw300; p.s768 = nullptr; p.numer = unum;
    p.W = Wpu; p.Wnum = Wnu; p.bias = bpu; p.bnum = bnu;
    p.out = px; p.M = N_USERC; p.K = 544; p.relu = 0; p.wsplit = 524;
    mma_fused_kernel<0><<<(N_USERC + 127) / 128, 256>>>(p);

    // ---- item projection: K padded 1302->1312 ----
    p.fi = ifi; p.ti = iti; p.id_emb = iide; p.feat_emb = ife;
    p.w300 = iw300; p.s768 = is768; p.numer = inum;
    p.W = Wpi; p.Wnum = Wni; p.bias = bpi; p.bnum = bni;
    p.out = px + (size_t)N_USERC * 64; p.M = M_ITEMC; p.K = 1312; p.wsplit = 1292;
    mma_fused_kernel<1><<<(M_ITEMC + 127) / 128, 256>>>(p);

    // ---- neighbor means (linear commutes with mean) ----
    mean_kernel<<<(MROWS * 32 + 255) / 256, 256>>>(neigh2, neigh1);

    // ---- agg = mean @ Wv0 + bv0 ----
    Args q{};
    q.A = pm; q.W = Wv; q.bias = bv; q.out = pagg; q.M = MROWS; q.K = 64; q.relu = 0;
    mma_fused_kernel<2><<<(MROWS + 127) / 128, 256>>>(q);

    // ---- layer 0: h = relu([self, agg] @ Ww0 + bw0) ----
    Args s{};
    s.neigh1 = neigh1; s.seeds = seeds; s.right = pagg;
    s.W = Ww; s.bias = bw; s.out = ph; s.M = MROWS; s.K = 128; s.relu = 1;
    mma_fused_kernel<3><<<(MROWS + 127) / 128, 256>>>(s);

    // ---- mean over h1 per seed ----
    meanh_kernel<<<(BSEED * 32 + 255) / 256, 256>>>();

    // ---- agg1 = mh @ Wv1 + bv1 ----
    q.A = pmh; q.W = Wv + 64 * 64; q.bias = bv + 64; q.out = pagg1;
    q.M = BSEED; q.K = 64; q.relu = 0;
    mma_fused_kernel<2><<<(BSEED + 127) / 128, 256>>>(q);

    // ---- layer 1: out = [h0, agg1] @ Ww1 + bw1 ----
    Args t{};
    t.A = ph + (size_t)M1ROWS * 64; t.right = pagg1;
    t.W = Ww + 128 * 64; t.bias = bw + 64; t.out = out;
    t.M = BSEED; t.K = 128; t.relu = 0;
    mma_fused_kernel<4><<<(BSEED + 127) / 128, 256>>>(t);
}

// round 3
// speedup vs baseline: 1.4545x; 1.0745x over previous
#include <cuda_runtime.h>
#include <cstdint>
#include <cstddef>

#define N_USERC 100000
#define M_ITEMC 50000
#define N_NODEC 150000
#define DD      64
#define BSEED   2048
#define SNB     20
#define M1ROWS  (BSEED*SNB)          // 40960
#define MROWS   (BSEED*SNB + BSEED)  // 43008
#define NFEAT   30000
#define VOCABC  20000

// ---------------- device scratch ----------
__device__ float g_x[(size_t)N_NODEC * DD];
__device__ float g_h[(size_t)MROWS * DD];
__device__ float g_pfe_u[(size_t)NFEAT * 64];
__device__ float g_pfe_i[(size_t)NFEAT * 64];
__device__ float g_pw_u[(size_t)VOCABC * 192];
__device__ float g_pw_i[(size_t)VOCABC * 192];

__device__ __forceinline__ uint32_t f2tf(float v) {
    uint32_t r; asm("cvt.rna.tf32.f32 %0, %1;" : "=r"(r) : "f"(v)); return r;
}
__device__ __forceinline__ void mma_tf32(float c[4],
    uint32_t a0, uint32_t a1, uint32_t a2, uint32_t a3, uint32_t b0, uint32_t b1)
{
    asm volatile(
        "mma.sync.aligned.m16n8k8.row.col.f32.tf32.tf32.f32 "
        "{%0,%1,%2,%3},{%4,%5,%6,%7},{%8,%9},{%0,%1,%2,%3};"
        : "+f"(c[0]), "+f"(c[1]), "+f"(c[2]), "+f"(c[3])
        : "r"(a0), "r"(a1), "r"(a2), "r"(a3), "r"(b0), "r"(b1));
}

// compute one 16-wide K tile from As[128][20], Bs[16][72]
__device__ __forceinline__ void compute_tile16(float c[2][4][4],
    const uint32_t (*As)[20], const uint32_t (*Bs)[72], int wm, int wn, int lane)
{
    const int r0 = lane >> 2, q = lane & 3;
#pragma unroll
    for (int ks = 0; ks < 2; ks++) {
        const int kb = ks * 8;
        uint32_t a[2][4], b[4][2];
#pragma unroll
        for (int mi = 0; mi < 2; mi++) {
            int mr = wm * 32 + mi * 16 + r0;
            a[mi][0] = As[mr][kb + q];
            a[mi][1] = As[mr + 8][kb + q];
            a[mi][2] = As[mr][kb + q + 4];
            a[mi][3] = As[mr + 8][kb + q + 4];
        }
#pragma unroll
        for (int ni = 0; ni < 4; ni++) {
            int nc = wn * 32 + ni * 8 + r0;
            b[ni][0] = Bs[kb + q][nc];
            b[ni][1] = Bs[kb + q + 4][nc];
        }
#pragma unroll
        for (int mi = 0; mi < 2; mi++)
#pragma unroll
            for (int ni = 0; ni < 4; ni++)
                mma_tf32(c[mi][ni], a[mi][0], a[mi][1], a[mi][2], a[mi][3],
                         b[ni][0], b[ni][1]);
    }
}

// same but A resident in a full-K [128][68] buffer, tile at kbase
__device__ __forceinline__ void compute_tile68(float c[2][4][4],
    const uint32_t (*Asrc)[68], int kbase, const uint32_t (*Bs)[72],
    int wm, int wn, int lane)
{
    const int r0 = lane >> 2, q = lane & 3;
#pragma unroll
    for (int ks = 0; ks < 2; ks++) {
        const int kb = ks * 8;
        uint32_t a[2][4], b[4][2];
#pragma unroll
        for (int mi = 0; mi < 2; mi++) {
            int mr = wm * 32 + mi * 16 + r0;
            a[mi][0] = Asrc[mr][kbase + kb + q];
            a[mi][1] = Asrc[mr + 8][kbase + kb + q];
            a[mi][2] = Asrc[mr][kbase + kb + q + 4];
            a[mi][3] = Asrc[mr + 8][kbase + kb + q + 4];
        }
#pragma unroll
        for (int ni = 0; ni < 4; ni++) {
            int nc = wn * 32 + ni * 8 + r0;
            b[ni][0] = Bs[kb + q][nc];
            b[ni][1] = Bs[kb + q + 4][nc];
        }
#pragma unroll
        for (int mi = 0; mi < 2; mi++)
#pragma unroll
            for (int ni = 0; ni < 4; ni++)
                mma_tf32(c[mi][ni], a[mi][0], a[mi][1], a[mi][2], a[mi][3],
                         b[ni][0], b[ni][1]);
    }
}

// ============ table precompute: out[y] = oscale * A @ W[y] ==================
__global__ void __launch_bounds__(256) gemm_simple(
    const float* __restrict__ A, const float* __restrict__ W,
    float* __restrict__ outp, int M, int K, int ostride, float oscale,
    int wsk, int osn)
{
    __shared__ uint32_t As[128][20];
    __shared__ uint32_t Bs[16][72];
    W    += (size_t)blockIdx.y * wsk;
    outp += (size_t)blockIdx.y * osn;

    const int tid = threadIdx.x, lane = tid & 31, wid = tid >> 5;
    const int wm = wid >> 1, wn = wid & 1;
    const int m0 = blockIdx.x * 128;

    float c[2][4][4];
#pragma unroll
    for (int a = 0; a < 2; a++)
#pragma unroll
        for (int b = 0; b < 4; b++)
#pragma unroll
            for (int d = 0; d < 4; d++) c[a][b][d] = 0.f;

    for (int k0 = 0; k0 < K; k0 += 16) {
        __syncthreads();
        for (int i = tid; i < 16 * 64; i += 256) {
            int kk = i >> 6, n = i & 63, r = k0 + kk;
            Bs[kk][n] = f2tf((r < K) ? W[(size_t)r * 64 + n] : 0.f);
        }
        for (int i = tid; i < 128 * 16; i += 256) {
            int ln = i >> 4, kk = i & 15;
            int r = m0 + ln, col = k0 + kk;
            float v = 0.f;
            if (r < M && col < K) v = __ldg(A + (size_t)r * K + col);
            As[ln][kk] = f2tf(v);
        }
        __syncthreads();
        compute_tile16(c, As, Bs, wm, wn, lane);
    }

    const int r0 = lane >> 2, q = lane & 3;
#pragma unroll
    for (int mi = 0; mi < 2; mi++)
#pragma unroll
        for (int ni = 0; ni < 4; ni++) {
            int col = wn * 32 + ni * 8 + 2 * q;
            int row = m0 + wm * 32 + mi * 16 + r0;
#pragma unroll
            for (int h = 0; h < 2; h++) {
                int rr = row + h * 8;
                if (rr < M) {
                    float2 o = make_float2(c[mi][ni][h * 2] * oscale,
                                           c[mi][ni][h * 2 + 1] * oscale);
                    *reinterpret_cast<float2*>(outp + (size_t)rr * ostride + col) = o;
                }
            }
        }
}

// ============ stage 1: fused gather + dense projection ======================
// dense K layout: [0,64) id | [64,368) w300 (300 valid) | [368,1136) s768 (item)
template<int ITEM>
__global__ void __launch_bounds__(256) stage1_kernel(
    const int* __restrict__ fi, const int* __restrict__ ti,
    const float* __restrict__ id_emb, const float* __restrict__ w300,
    const float* __restrict__ s768, const float* __restrict__ numer,
    const float* __restrict__ Wnum, const float* __restrict__ Wp,
    const float* __restrict__ bproj, const float* __restrict__ bnum,
    const float* __restrict__ Pfe, const float* __restrict__ Pw,
    float* __restrict__ outX)
{
    __shared__ uint32_t As[128][20];
    __shared__ uint32_t Bs[16][72];
    __shared__ float    gsum[128][64];
    __shared__ float    sbias[64];

    const int tid = threadIdx.x, lane = tid & 31, wid = tid >> 5;
    const int wm = wid >> 1, wn = wid & 1;
    const int m0 = blockIdx.x * 128;
    const int bound = ITEM ? M_ITEMC : N_USERC;
    const int KTOT = ITEM ? 1136 : 368;

    if (tid < 64) sbias[tid] = bproj[tid] + bnum[tid];

    // ---- gather phase: feat/text tables + numeric, into gsum ----
#pragma unroll 1
    for (int rr = 0; rr < 16; ++rr) {
        int ln = wid * 16 + rr;
        int node = m0 + ln;
        float sx = 0.f, sy = 0.f;
        if (node < bound) {
#pragma unroll
            for (int d = 0; d < 10; d++) {
                float nv = __ldg(numer + (size_t)node * 10 + d);
                float2 w = *reinterpret_cast<const float2*>(Wnum + (size_t)d * 64 + lane * 2);
                sx += nv * w.x; sy += nv * w.y;
            }
#pragma unroll
            for (int j = 0; j < 10; j++) {
                int ix = __ldg(fi + (size_t)node * 10 + j);
                float2 v = *reinterpret_cast<const float2*>(Pfe + (size_t)ix * 64 + lane * 2);
                sx += v.x; sy += v.y;
            }
#pragma unroll
            for (int s = 0; s < 3; s++) {
                const int* tb = ti + (size_t)node * 24 + s * 8;
#pragma unroll
                for (int t = 0; t < 8; t++) {
                    int ix = __ldg(tb + t);
                    float2 v = *reinterpret_cast<const float2*>(
                        Pw + (size_t)ix * 192 + s * 64 + lane * 2);
                    sx += v.x; sy += v.y;
                }
            }
        }
        gsum[ln][lane * 2]     = sx;
        gsum[ln][lane * 2 + 1] = sy;
    }

    // ---- dense K-loop ----
    float c[2][4][4];
#pragma unroll
    for (int a = 0; a < 2; a++)
#pragma unroll
        for (int b = 0; b < 4; b++)
#pragma unroll
            for (int d = 0; d < 4; d++) c[a][b][d] = 0.f;

    for (int k0 = 0; k0 < KTOT; k0 += 16) {
        __syncthreads();
        for (int i = tid; i < 16 * 64; i += 256) {
            int kk = i >> 6, n = i & 63, r = k0 + kk;
            float v = 0.f;
            if (r < 64)                     v = Wp[(size_t)r * 64 + n];
            else if (r < 364)               v = Wp[(size_t)(r + 160) * 64 + n];
            else if (ITEM && r >= 368)      v = Wp[(size_t)(r + 156) * 64 + n];
            Bs[kk][n] = f2tf(v);
        }
        for (int i = tid; i < 128 * 16; i += 256) {
            int ln = i >> 4, kk = i & 15;
            int r = m0 + ln, col = k0 + kk;
            float v = 0.f;
            if (r < bound) {
                if (col < 64) {
                    v = __ldg(id_emb + (size_t)r * 64 + col);
                } else if (col < 364) {
                    int cc = col - 64;
                    if (cc < 300) v = __ldg(w300 + (size_t)r * 300 + cc);
                } else if (ITEM && col >= 368) {
                    v = __ldg(s768 + (size_t)r * 768 + (col - 368));
                }
            }
            As[ln][kk] = f2tf(v);
        }
        __syncthreads();
        compute_tile16(c, As, Bs, wm, wn, lane);
    }

    // ---- epilogue: + gsum + bias ----
    const int r0 = lane >> 2, q = lane & 3;
#pragma unroll
    for (int mi = 0; mi < 2; mi++)
#pragma unroll
        for (int ni = 0; ni < 4; ni++) {
            int col = wn * 32 + ni * 8 + 2 * q;
            int lr = wm * 32 + mi * 16 + r0;
#pragma unroll
            for (int h = 0; h < 2; h++) {
                int lrow = lr + h * 8;
                int rr = m0 + lrow;
                if (rr < bound) {
                    float v0 = c[mi][ni][h * 2]     + gsum[lrow][col]     + sbias[col];
                    float v1 = c[mi][ni][h * 2 + 1] + gsum[lrow][col + 1] + sbias[col + 1];
                    *reinterpret_cast<float2*>(outX + (size_t)rr * 64 + col) =
                        make_float2(v0, v1);
                }
            }
        }
}

// ============ fused SAGE layer: mean-gather -> aggGEMM -> concatGEMM ========
template<int L0>
__global__ void __launch_bounds__(256) layer_kernel(
    const int* __restrict__ neigh2, const int* __restrict__ neigh1,
    const int* __restrict__ seeds,
    const float* __restrict__ Wv, const float* __restrict__ bv,
    const float* __restrict__ Ww, const float* __restrict__ bw,
    float* __restrict__ outp, int M, int relu)
{
    extern __shared__ uint32_t dsm[];
    uint32_t (*Ms)[68] = (uint32_t(*)[68])dsm;               // mean -> agg
    uint32_t (*Ss)[68] = (uint32_t(*)[68])(dsm + 128 * 68);  // self
    uint32_t (*Bs)[72] = (uint32_t(*)[72])(dsm + 2 * 128 * 68);
    float* sbv = (float*)(dsm + 2 * 128 * 68 + 16 * 72);
    float* sbw = sbv + 64;

    const int tid = threadIdx.x, lane = tid & 31, wid = tid >> 5;
    const int wm = wid >> 1, wn = wid & 1;
    const int m0 = blockIdx.x * 128;

    if (tid < 64) { sbv[tid] = bv[tid]; sbw[tid] = bw[tid]; }

    // ---- phase 1: gather mean + self ----
#pragma unroll 1
    for (int rr = 0; rr < 16; ++rr) {
        int ln = wid * 16 + rr;
        int r = m0 + ln;
        float ax = 0.f, ay = 0.f;
        float2 self = make_float2(0.f, 0.f);
        if (r < M) {
            if (L0) {
                const int* idx = (r < M1ROWS) ? (neigh2 + (size_t)r * SNB)
                                              : (neigh1 + (size_t)(r - M1ROWS) * SNB);
#pragma unroll
                for (int j = 0; j < SNB; j++) {
                    int n = __ldg(idx + j);
                    float2 v = *reinterpret_cast<const float2*>(g_x + (size_t)n * 64 + lane * 2);
                    ax += v.x; ay += v.y;
                }
                int sn = (r < M1ROWS) ? __ldg(neigh1 + r) : __ldg(seeds + r - M1ROWS);
                self = *reinterpret_cast<const float2*>(g_x + (size_t)sn * 64 + lane * 2);
            } else {
#pragma unroll
                for (int j = 0; j < SNB; j++) {
                    float2 v = *reinterpret_cast<const float2*>(
                        g_h + (size_t)(r * SNB + j) * 64 + lane * 2);
                    ax += v.x; ay += v.y;
                }
                self = *reinterpret_cast<const float2*>(
                    g_h + (size_t)(M1ROWS + r) * 64 + lane * 2);
            }
            ax *= 0.05f; ay *= 0.05f;
        }
        Ms[ln][lane * 2]     = f2tf(ax);
        Ms[ln][lane * 2 + 1] = f2tf(ay);
        Ss[ln][lane * 2]     = f2tf(self.x);
        Ss[ln][lane * 2 + 1] = f2tf(self.y);
    }

    // ---- phase 2: agg = mean @ Wv ----
    float ca[2][4][4];
#pragma unroll
    for (int a = 0; a < 2; a++)
#pragma unroll
        for (int b = 0; b < 4; b++)
#pragma unroll
            for (int d = 0; d < 4; d++) ca[a][b][d] = 0.f;

    for (int k0 = 0; k0 < 64; k0 += 16) {
        __syncthreads();
        for (int i = tid; i < 16 * 64; i += 256) {
            int kk = i >> 6, n = i & 63;
            Bs[kk][n] = f2tf(Wv[(size_t)(k0 + kk) * 64 + n]);
        }
        __syncthreads();
        compute_tile68(ca, Ms, k0, Bs, wm, wn, lane);
    }
    __syncthreads();   // all reads of Ms done

    // ---- phase 3: write agg (+bv) into Ms ----
    {
        const int r0 = lane >> 2, q = lane & 3;
#pragma unroll
        for (int mi = 0; mi < 2; mi++)
#pragma unroll
            for (int ni = 0; ni < 4; ni++) {
                int col = wn * 32 + ni * 8 + 2 * q;
                int lr = wm * 32 + mi * 16 + r0;
#pragma unroll
                for (int h = 0; h < 2; h++) {
                    int lrow = lr + h * 8;
                    Ms[lrow][col]     = f2tf(ca[mi][ni][h * 2]     + sbv[col]);
                    Ms[lrow][col + 1] = f2tf(ca[mi][ni][h * 2 + 1] + sbv[col + 1]);
                }
            }
    }
    __syncthreads();

    // ---- phase 4: h = [self | agg] @ Ww (K=128) ----
    float ch[2][4][4];
#pragma unroll
    for (int a = 0; a < 2; a++)
#pragma unroll
        for (int b = 0; b < 4; b++)
#pragma unroll
            for (int d = 0; d < 4; d++) ch[a][b][d] = 0.f;

    for (int k0 = 0; k0 < 128; k0 += 16) {
        __syncthreads();
        for (int i = tid; i < 16 * 64; i += 256) {
            int kk = i >> 6, n = i & 63;
            Bs[kk][n] = f2tf(Ww[(size_t)(k0 + kk) * 64 + n]);
        }
        __syncthreads();
        if (k0 < 64) compute_tile68(ch, Ss, k0,      Bs, wm, wn, lane);
        else         compute_tile68(ch, Ms, k0 - 64, Bs, wm, wn, lane);
    }

    // ---- epilogue ----
    const int r0 = lane >> 2, q = lane & 3;
#pragma unroll
    for (int mi = 0; mi < 2; mi++)
#pragma unroll
        for (int ni = 0; ni < 4; ni++) {
            int col = wn * 32 + ni * 8 + 2 * q;
            int row = m0 + wm * 32 + mi * 16 + r0;
#pragma unroll
            for (int h = 0; h < 2; h++) {
                int rr = row + h * 8;
                if (rr < M) {
                    float v0 = ch[mi][ni][h * 2]     + sbw[col];
                    float v1 = ch[mi][ni][h * 2 + 1] + sbw[col + 1];
                    if (relu) { v0 = fmaxf(v0, 0.f); v1 = fmaxf(v1, 0.f); }
                    *reinterpret_cast<float2*>(outp + (size_t)rr * 64 + col) =
                        make_float2(v0, v1);
                }
            }
        }
}

// ============================ launch =========================================
extern "C" void kernel_launch(void* const* d_in, const int* in_sizes, int n_in,
                              void* d_out, int out_size)
{
    const int*   seeds  = (const int*)d_in[0];
    const int*   neigh1 = (const int*)d_in[1];
    const int*   neigh2 = (const int*)d_in[2];
    const int*   ufi    = (const int*)d_in[3];
    const int*   ifi    = (const int*)d_in[4];
    const int*   uti    = (const int*)d_in[5];
    const int*   iti    = (const int*)d_in[6];
    const float* uide   = (const float*)d_in[7];
    const float* iide   = (const float*)d_in[8];
    const float* ufe    = (const float*)d_in[9];
    const float* ife    = (const float*)d_in[10];
    const float* wemb   = (const float*)d_in[11];
    const float* uw300  = (const float*)d_in[12];
    const float* iw300  = (const float*)d_in[13];
    const float* is768  = (const float*)d_in[14];
    const float* unum   = (const float*)d_in[15];
    const float* inum   = (const float*)d_in[16];
    const float* Wnu    = (const float*)d_in[17];
    const float* bnu    = (const float*)d_in[18];
    const float* Wni    = (const float*)d_in[19];
    const float* bni    = (const float*)d_in[20];
    const float* Wpu    = (const float*)d_in[21];
    const float* bpu    = (const float*)d_in[22];
    const float* Wpi    = (const float*)d_in[23];
    const float* bpi    = (const float*)d_in[24];
    const float* Ww     = (const float*)d_in[25];
    const float* bw     = (const float*)d_in[26];
    const float* Wv     = (const float*)d_in[27];
    const float* bv     = (const float*)d_in[28];
    float* out = (float*)d_out;

    float *px, *ph, *pfeu, *pfei, *pwu, *pwi;
    cudaGetSymbolAddress((void**)&px,   g_x);
    cudaGetSymbolAddress((void**)&ph,   g_h);
    cudaGetSymbolAddress((void**)&pfeu, g_pfe_u);
    cudaGetSymbolAddress((void**)&pfei, g_pfe_i);
    cudaGetSymbolAddress((void**)&pwu,  g_pw_u);
    cudaGetSymbolAddress((void**)&pwi,  g_pw_i);

    static const int SMEM_L = (2 * 128 * 68 + 16 * 72 + 128) * 4;
    cudaFuncSetAttribute(layer_kernel<1>,
                         cudaFuncAttributeMaxDynamicSharedMemorySize, SMEM_L);
    cudaFuncSetAttribute(layer_kernel<0>,
                         cudaFuncAttributeMaxDynamicSharedMemorySize, SMEM_L);

    // ---- table precompute ----
    gemm_simple<<<dim3((NFEAT + 127) / 128, 1), 256>>>(
        ufe, Wpu + 64 * 64, pfeu, NFEAT, 64, 64, 0.1f, 0, 0);
    gemm_simple<<<dim3((NFEAT + 127) / 128, 1), 256>>>(
        ife, Wpi + 64 * 64, pfei, NFEAT, 64, 64, 0.1f, 0, 0);
    gemm_simple<<<dim3((VOCABC + 127) / 128, 3), 256>>>(
        wemb, Wpu + 128 * 64, pwu, VOCABC, 32, 192, 0.125f, 32 * 64, 64);
    gemm_simple<<<dim3((VOCABC + 127) / 128, 3), 256>>>(
        wemb, Wpi + 128 * 64, pwi, VOCABC, 32, 192, 0.125f, 32 * 64, 64);

    // ---- stage 1: node embeddings ----
    stage1_kernel<0><<<(N_USERC + 127) / 128, 256>>>(
        ufi, uti, uide, uw300, nullptr, unum, Wnu, Wpu, bpu, bnu,
        pfeu, pwu, px);
    stage1_kernel<1><<<(M_ITEMC + 127) / 128, 256>>>(
        ifi, iti, iide, iw300, is768, inum, Wni, Wpi, bpi, bni,
        pfei, pwi, px + (size_t)N_USERC * 64);

    // ---- layer 0 (fused mean+agg+concat GEMM), relu ----
    layer_kernel<1><<<(MROWS + 127) / 128, 256, SMEM_L>>>(
        neigh2, neigh1, seeds, Wv, bv, Ww, bw, ph, MROWS, 1);

    // ---- layer 1, no relu, writes output ----
    layer_kernel<0><<<(BSEED + 127) / 128, 256, SMEM_L>>>(
        nullptr, nullptr, nullptr, Wv + 64 * 64, bv + 64,
        Ww + 128 * 64, bw + 64, out, BSEED, 0);
}

// round 5
// speedup vs baseline: 3.2673x; 2.2463x over previous
#include <cuda_runtime.h>
#include <cstdint>
#include <cstddef>

#define N_USERC 100000
#define M_ITEMC 50000
#define N_NODEC 150000
#define DD      64
#define BSEED   2048
#define SNB     20
#define M1ROWS  (BSEED*SNB)          // 40960
#define MROWS   (BSEED*SNB + BSEED)  // 43008
#define NFEAT   30000
#define VOCABC  20000

// ---------------- device scratch ----------
__device__ float g_x[(size_t)N_NODEC * DD];
__device__ float g_h[(size_t)MROWS * DD];
__device__ float g_pfe_u[(size_t)NFEAT * 64];
__device__ float g_pfe_i[(size_t)NFEAT * 64];
__device__ float g_pw_u[(size_t)VOCABC * 192];
__device__ float g_pw_i[(size_t)VOCABC * 192];
__device__ float g_gs[(size_t)N_NODEC * 64];
__device__ float g_Bu[(size_t)384 * 64];
__device__ float g_Bi[(size_t)1152 * 64];

__device__ __forceinline__ uint32_t f2tf(float v) {
    uint32_t r; asm("cvt.rna.tf32.f32 %0, %1;" : "=r"(r) : "f"(v)); return r;
}
__device__ __forceinline__ void mma_tf32(float c[4],
    uint32_t a0, uint32_t a1, uint32_t a2, uint32_t a3, uint32_t b0, uint32_t b1)
{
    asm volatile(
        "mma.sync.aligned.m16n8k8.row.col.f32.tf32.tf32.f32 "
        "{%0,%1,%2,%3},{%4,%5,%6,%7},{%8,%9},{%0,%1,%2,%3};"
        : "+f"(c[0]), "+f"(c[1]), "+f"(c[2]), "+f"(c[3])
        : "r"(a0), "r"(a1), "r"(a2), "r"(a3), "r"(b0), "r"(b1));
}
__device__ __forceinline__ uint32_t smem_u32(const void* p) {
    return (uint32_t)__cvta_generic_to_shared(p);
}
__device__ __forceinline__ void cp16(uint32_t dst, const void* src, int bytes) {
    asm volatile("cp.async.ca.shared.global [%0], [%1], 16, %2;\n"
                 :: "r"(dst), "l"(src), "r"(bytes));
}
__device__ __forceinline__ void cp_commit() {
    asm volatile("cp.async.commit_group;\n");
}
template<int N> __device__ __forceinline__ void cp_wait() {
    asm volatile("cp.async.wait_group %0;\n" :: "n"(N));
}

// =================== pipelined GEMM: out = scale*A@B (+gs) ==================
// A assembled from up to 3 row-major regions (gaps -> zero). B dense [K x 64].
struct PArgs {
    const float *A0, *A1, *A2;
    int a0e, a1b, a1e, a2b, a2e;
    int a0rs, a1rs, a2rs;
    const float* B;  long bsy;     // per-blockIdx.y B offset (floats)
    const float* gs;               // epilogue add [row*64+col] or null
    float* out; int ostride; long osy;
    int M, K; float scale;
};

__device__ __forceinline__ void compute32(float c[2][4][4],
    const float* Ad, const float* Bd, int wm, int wn, int lane)
{
    const int r0 = lane >> 2, q = lane & 3;
#pragma unroll
    for (int ks = 0; ks < 4; ks++) {
        const int kb = ks * 8;
        uint32_t a[2][4], b[4][2];
#pragma unroll
        for (int mi = 0; mi < 2; mi++) {
            int mr = wm * 32 + mi * 16 + r0;
            a[mi][0] = f2tf(Ad[mr * 36 + kb + q]);
            a[mi][1] = f2tf(Ad[(mr + 8) * 36 + kb + q]);
            a[mi][2] = f2tf(Ad[mr * 36 + kb + q + 4]);
            a[mi][3] = f2tf(Ad[(mr + 8) * 36 + kb + q + 4]);
        }
#pragma unroll
        for (int ni = 0; ni < 4; ni++) {
            int nc = wn * 32 + ni * 8 + r0;
            b[ni][0] = f2tf(Bd[(kb + q) * 72 + nc]);
            b[ni][1] = f2tf(Bd[(kb + q + 4) * 72 + nc]);
        }
#pragma unroll
        for (int mi = 0; mi < 2; mi++)
#pragma unroll
            for (int ni = 0; ni < 4; ni++)
                mma_tf32(c[mi][ni], a[mi][0], a[mi][1], a[mi][2], a[mi][3],
                         b[ni][0], b[ni][1]);
    }
}

__global__ void __launch_bounds__(256) pgemm(PArgs p)
{
    extern __shared__ float smp[];
    float* Asm = smp;                      // [3][128*36]
    float* Bsm = smp + 3 * 128 * 36;       // [3][32*72]

    const int tid = threadIdx.x, lane = tid & 31, wid = tid >> 5;
    const int wm = wid >> 1, wn = wid & 1;
    const int m0 = blockIdx.x * 128;
    const float* Bp = p.B + (size_t)blockIdx.y * p.bsy;

    auto issue = [&](int tile, int slot) {
        const int k0 = tile * 32;
        float* Ad = Asm + slot * (128 * 36);
        float* Bd = Bsm + slot * (32 * 72);
        // A: 128 rows x 8 chunks of 4 floats = 1024 chunks
#pragma unroll
        for (int j = 0; j < 4; j++) {
            int ch = tid + j * 256;
            int r = ch >> 3, cq = ch & 7;
            int col = k0 + cq * 4;
            int row = m0 + r;
            const float* src = p.A0; int bytes = 0;
            if (row < p.M) {
                if (col < p.a0e) {
                    src = p.A0 + (size_t)row * p.a0rs + col; bytes = 16;
                } else if (col >= p.a1b && col < p.a1e) {
                    src = p.A1 + (size_t)row * p.a1rs + (col - p.a1b); bytes = 16;
                } else if (col >= p.a2b && col < p.a2e) {
                    src = p.A2 + (size_t)row * p.a2rs + (col - p.a2b); bytes = 16;
                }
            }
            cp16(smem_u32(Ad + r * 36 + cq * 4), src, bytes);
        }
        // B: 32 rows x 16 chunks of 4 floats = 512 chunks
#pragma unroll
        for (int j = 0; j < 2; j++) {
            int cb = tid + j * 256;
            int kr = cb >> 4, cq = cb & 15;
            cp16(smem_u32(Bd + kr * 72 + cq * 4),
                 Bp + (size_t)(k0 + kr) * 64 + cq * 4, 16);
        }
    };

    float c[2][4][4];
#pragma unroll
    for (int a = 0; a < 2; a++)
#pragma unroll
        for (int b = 0; b < 4; b++)
#pragma unroll
            for (int d = 0; d < 4; d++) c[a][b][d] = 0.f;

    const int nt = p.K / 32;
    issue(0, 0); cp_commit();
    if (nt > 1) { issue(1, 1); cp_commit(); }

    for (int t = 0; t < nt; t++) {
        // tile t's group must be complete; tile t+1 (if any) may stay in flight
        if (t + 1 < nt) cp_wait<1>(); else cp_wait<0>();
        __syncthreads();
        if (t + 2 < nt) { issue(t + 2, (t + 2) % 3); cp_commit(); }
        const float* Ad = Asm + (t % 3) * (128 * 36);
        const float* Bd = Bsm + (t % 3) * (32 * 72);
        compute32(c, Ad, Bd, wm, wn, lane);
    }

    float* outp = p.out + (size_t)blockIdx.y * p.osy;
    const int r0 = lane >> 2, q = lane & 3;
#pragma unroll
    for (int mi = 0; mi < 2; mi++)
#pragma unroll
        for (int ni = 0; ni < 4; ni++) {
            int col = wn * 32 + ni * 8 + 2 * q;
            int row = m0 + wm * 32 + mi * 16 + r0;
#pragma unroll
            for (int h = 0; h < 2; h++) {
                int rr = row + h * 8;
                if (rr < p.M) {
                    float v0 = c[mi][ni][h * 2]     * p.scale;
                    float v1 = c[mi][ni][h * 2 + 1] * p.scale;
                    if (p.gs) {
                        float2 g = *reinterpret_cast<const float2*>(
                            p.gs + (size_t)rr * 64 + col);
                        v0 += g.x; v1 += g.y;
                    }
                    *reinterpret_cast<float2*>(outp + (size_t)rr * p.ostride + col) =
                        make_float2(v0, v1);
                }
            }
        }
}

// =================== pack padded dense B matrices ===========================
__global__ void pack_kernel(const float* __restrict__ Wpu,
                            const float* __restrict__ Wpi)
{
    int i = blockIdx.x * 256 + threadIdx.x;
    if (i < 384 * 64) {
        int r = i >> 6, n = i & 63; float v = 0.f;
        if (r < 64)       v = Wpu[(size_t)r * 64 + n];
        else if (r < 364) v = Wpu[(size_t)(r + 160) * 64 + n];
        g_Bu[i] = v;
    }
    if (i < 1152 * 64) {
        int r = i >> 6, n = i & 63; float v = 0.f;
        if (r < 64)                    v = Wpi[(size_t)r * 64 + n];
        else if (r < 364)              v = Wpi[(size_t)(r + 160) * 64 + n];
        else if (r >= 368 && r < 1136) v = Wpi[(size_t)(r + 156) * 64 + n];
        g_Bi[i] = v;
    }
}

// ========== gather kernel: gs = bias + numeric@Wnum + feat/text table sums ==
__global__ void __launch_bounds__(256) gather_kernel(
    const int* __restrict__ fi, const int* __restrict__ ti,
    const float* __restrict__ numer, const float* __restrict__ Wnum,
    const float* __restrict__ bproj, const float* __restrict__ bnum,
    const float* __restrict__ Pfe, const float* __restrict__ Pw,
    float* __restrict__ gs, int M)
{
    int w = (blockIdx.x * blockDim.x + threadIdx.x) >> 5;
    int lane = threadIdx.x & 31;
    if (w >= M) return;
    int c2 = lane * 2;

    float2 acc;
    acc.x = __ldg(bproj + c2)     + __ldg(bnum + c2);
    acc.y = __ldg(bproj + c2 + 1) + __ldg(bnum + c2 + 1);

#pragma unroll
    for (int d = 0; d < 10; d++) {
        float nv = __ldg(numer + (size_t)w * 10 + d);
        float2 ww = *reinterpret_cast<const float2*>(Wnum + (size_t)d * 64 + c2);
        acc.x += nv * ww.x; acc.y += nv * ww.y;
    }
#pragma unroll
    for (int j = 0; j < 10; j++) {
        int ix = __ldg(fi + (size_t)w * 10 + j);
        float2 v = *reinterpret_cast<const float2*>(Pfe + (size_t)ix * 64 + c2);
        acc.x += v.x; acc.y += v.y;
    }
#pragma unroll
    for (int s = 0; s < 3; s++) {
#pragma unroll
        for (int t = 0; t < 8; t++) {
            int ix = __ldg(ti + (size_t)w * 24 + s * 8 + t);
            float2 v = *reinterpret_cast<const float2*>(
                Pw + (size_t)ix * 192 + s * 64 + c2);
            acc.x += v.x; acc.y += v.y;
        }
    }
    *reinterpret_cast<float2*>(gs + (size_t)w * 64 + c2) = acc;
}

// =================== fused SAGE layer ======================================
__device__ __forceinline__ void compute_tile68(float c[2][4][4],
    const uint32_t (*Asrc)[68], int kbase, const uint32_t (*Bs)[72],
    int wm, int wn, int lane)
{
    const int r0 = lane >> 2, q = lane & 3;
#pragma unroll
    for (int ks = 0; ks < 2; ks++) {
        const int kb = ks * 8;
        uint32_t a[2][4], b[4][2];
#pragma unroll
        for (int mi = 0; mi < 2; mi++) {
            int mr = wm * 32 + mi * 16 + r0;
            a[mi][0] = Asrc[mr][kbase + kb + q];
            a[mi][1] = Asrc[mr + 8][kbase + kb + q];
            a[mi][2] = Asrc[mr][kbase + kb + q + 4];
            a[mi][3] = Asrc[mr + 8][kbase + kb + q + 4];
        }
#pragma unroll
        for (int ni = 0; ni < 4; ni++) {
            int nc = wn * 32 + ni * 8 + r0;
            b[ni][0] = Bs[kb + q][nc];
            b[ni][1] = Bs[kb + q + 4][nc];
        }
#pragma unroll
        for (int mi = 0; mi < 2; mi++)
#pragma unroll
            for (int ni = 0; ni < 4; ni++)
                mma_tf32(c[mi][ni], a[mi][0], a[mi][1], a[mi][2], a[mi][3],
                         b[ni][0], b[ni][1]);
    }
}

template<int L0>
__global__ void __launch_bounds__(256) layer_kernel(
    const int* __restrict__ neigh2, const int* __restrict__ neigh1,
    const int* __restrict__ seeds,
    const float* __restrict__ Wv, const float* __restrict__ bv,
    const float* __restrict__ Ww, const float* __restrict__ bw,
    float* __restrict__ outp, int M, int relu)
{
    extern __shared__ uint32_t dsm[];
    uint32_t (*Ms)[68] = (uint32_t(*)[68])dsm;
    uint32_t (*Ss)[68] = (uint32_t(*)[68])(dsm + 128 * 68);
    uint32_t (*Bs)[72] = (uint32_t(*)[72])(dsm + 2 * 128 * 68);
    float* sbv = (float*)(dsm + 2 * 128 * 68 + 16 * 72);
    float* sbw = sbv + 64;

    const int tid = threadIdx.x, lane = tid & 31, wid = tid >> 5;
    const int wm = wid >> 1, wn = wid & 1;
    const int m0 = blockIdx.x * 128;

    if (tid < 64) { sbv[tid] = bv[tid]; sbw[tid] = bw[tid]; }

#pragma unroll 1
    for (int rr = 0; rr < 16; ++rr) {
        int ln = wid * 16 + rr;
        int r = m0 + ln;
        float ax = 0.f, ay = 0.f;
        float2 self = make_float2(0.f, 0.f);
        if (r < M) {
            if (L0) {
                const int* idx = (r < M1ROWS) ? (neigh2 + (size_t)r * SNB)
                                              : (neigh1 + (size_t)(r - M1ROWS) * SNB);
#pragma unroll
                for (int j = 0; j < SNB; j++) {
                    int n = __ldg(idx + j);
                    float2 v = *reinterpret_cast<const float2*>(g_x + (size_t)n * 64 + lane * 2);
                    ax += v.x; ay += v.y;
                }
                int sn = (r < M1ROWS) ? __ldg(neigh1 + r) : __ldg(seeds + r - M1ROWS);
                self = *reinterpret_cast<const float2*>(g_x + (size_t)sn * 64 + lane * 2);
            } else {
#pragma unroll
                for (int j = 0; j < SNB; j++) {
                    float2 v = *reinterpret_cast<const float2*>(
                        g_h + (size_t)(r * SNB + j) * 64 + lane * 2);
                    ax += v.x; ay += v.y;
                }
                self = *reinterpret_cast<const float2*>(
                    g_h + (size_t)(M1ROWS + r) * 64 + lane * 2);
            }
            ax *= 0.05f; ay *= 0.05f;
        }
        Ms[ln][lane * 2]     = f2tf(ax);
        Ms[ln][lane * 2 + 1] = f2tf(ay);
        Ss[ln][lane * 2]     = f2tf(self.x);
        Ss[ln][lane * 2 + 1] = f2tf(self.y);
    }

    float ca[2][4][4];
#pragma unroll
    for (int a = 0; a < 2; a++)
#pragma unroll
        for (int b = 0; b < 4; b++)
#pragma unroll
            for (int d = 0; d < 4; d++) ca[a][b][d] = 0.f;

    for (int k0 = 0; k0 < 64; k0 += 16) {
        __syncthreads();
        for (int i = tid; i < 16 * 64; i += 256) {
            int kk = i >> 6, n = i & 63;
            Bs[kk][n] = f2tf(Wv[(size_t)(k0 + kk) * 64 + n]);
        }
        __syncthreads();
        compute_tile68(ca, Ms, k0, Bs, wm, wn, lane);
    }
    __syncthreads();

    {
        const int r0 = lane >> 2, q = lane & 3;
#pragma unroll
        for (int mi = 0; mi < 2; mi++)
#pragma unroll
            for (int ni = 0; ni < 4; ni++) {
                int col = wn * 32 + ni * 8 + 2 * q;
                int lr = wm * 32 + mi * 16 + r0;
#pragma unroll
                for (int h = 0; h < 2; h++) {
                    int lrow = lr + h * 8;
                    Ms[lrow][col]     = f2tf(ca[mi][ni][h * 2]     + sbv[col]);
                    Ms[lrow][col + 1] = f2tf(ca[mi][ni][h * 2 + 1] + sbv[col + 1]);
                }
            }
    }
    __syncthreads();

    float ch[2][4][4];
#pragma unroll
    for (int a = 0; a < 2; a++)
#pragma unroll
        for (int b = 0; b < 4; b++)
#pragma unroll
            for (int d = 0; d < 4; d++) ch[a][b][d] = 0.f;

    for (int k0 = 0; k0 < 128; k0 += 16) {
        __syncthreads();
        for (int i = tid; i < 16 * 64; i += 256) {
            int kk = i >> 6, n = i & 63;
            Bs[kk][n] = f2tf(Ww[(size_t)(k0 + kk) * 64 + n]);
        }
        __syncthreads();
        if (k0 < 64) compute_tile68(ch, Ss, k0,      Bs, wm, wn, lane);
        else         compute_tile68(ch, Ms, k0 - 64, Bs, wm, wn, lane);
    }

    const int r0 = lane >> 2, q = lane & 3;
#pragma unroll
    for (int mi = 0; mi < 2; mi++)
#pragma unroll
        for (int ni = 0; ni < 4; ni++) {
            int col = wn * 32 + ni * 8 + 2 * q;
            int row = m0 + wm * 32 + mi * 16 + r0;
#pragma unroll
            for (int h = 0; h < 2; h++) {
                int rr = row + h * 8;
                if (rr < M) {
                    float v0 = ch[mi][ni][h * 2]     + sbw[col];
                    float v1 = ch[mi][ni][h * 2 + 1] + sbw[col + 1];
                    if (relu) { v0 = fmaxf(v0, 0.f); v1 = fmaxf(v1, 0.f); }
                    *reinterpret_cast<float2*>(outp + (size_t)rr * 64 + col) =
                        make_float2(v0, v1);
                }
            }
        }
}

// ============================ launch =========================================
extern "C" void kernel_launch(void* const* d_in, const int* in_sizes, int n_in,
                              void* d_out, int out_size)
{
    const int*   seeds  = (const int*)d_in[0];
    const int*   neigh1 = (const int*)d_in[1];
    const int*   neigh2 = (const int*)d_in[2];
    const int*   ufi    = (const int*)d_in[3];
    const int*   ifi    = (const int*)d_in[4];
    const int*   uti    = (const int*)d_in[5];
    const int*   iti    = (const int*)d_in[6];
    const float* uide   = (const float*)d_in[7];
    const float* iide   = (const float*)d_in[8];
    const float* ufe    = (const float*)d_in[9];
    const float* ife    = (const float*)d_in[10];
    const float* wemb   = (const float*)d_in[11];
    const float* uw300  = (const float*)d_in[12];
    const float* iw300  = (const float*)d_in[13];
    const float* is768  = (const float*)d_in[14];
    const float* unum   = (const float*)d_in[15];
    const float* inum   = (const float*)d_in[16];
    const float* Wnu    = (const float*)d_in[17];
    const float* bnu    = (const float*)d_in[18];
    const float* Wni    = (const float*)d_in[19];
    const float* bni    = (const float*)d_in[20];
    const float* Wpu    = (const float*)d_in[21];
    const float* bpu    = (const float*)d_in[22];
    const float* Wpi    = (const float*)d_in[23];
    const float* bpi    = (const float*)d_in[24];
    const float* Ww     = (const float*)d_in[25];
    const float* bw     = (const float*)d_in[26];
    const float* Wv     = (const float*)d_in[27];
    const float* bv     = (const float*)d_in[28];
    float* out = (float*)d_out;

    float *px, *ph, *pfeu, *pfei, *pwu, *pwi, *pgs, *pBu, *pBi;
    cudaGetSymbolAddress((void**)&px,   g_x);
    cudaGetSymbolAddress((void**)&ph,   g_h);
    cudaGetSymbolAddress((void**)&pfeu, g_pfe_u);
    cudaGetSymbolAddress((void**)&pfei, g_pfe_i);
    cudaGetSymbolAddress((void**)&pwu,  g_pw_u);
    cudaGetSymbolAddress((void**)&pwi,  g_pw_i);
    cudaGetSymbolAddress((void**)&pgs,  g_gs);
    cudaGetSymbolAddress((void**)&pBu,  g_Bu);
    cudaGetSymbolAddress((void**)&pBi,  g_Bi);

    static const int SMEM_P = (3 * 128 * 36 + 3 * 32 * 72) * 4;    // 82944
    static const int SMEM_L = (2 * 128 * 68 + 16 * 72 + 128) * 4;
    cudaFuncSetAttribute(pgemm, cudaFuncAttributeMaxDynamicSharedMemorySize, SMEM_P);
    cudaFuncSetAttribute(layer_kernel<1>,
                         cudaFuncAttributeMaxDynamicSharedMemorySize, SMEM_L);
    cudaFuncSetAttribute(layer_kernel<0>,
                         cudaFuncAttributeMaxDynamicSharedMemorySize, SMEM_L);

    // ---- pack dense padded B matrices ----
    pack_kernel<<<(1152 * 64 + 255) / 256, 256>>>(Wpu, Wpi);

    // ---- table precompute ----
    PArgs t{};
    t.A0 = ufe; t.a0e = 64; t.a0rs = 64;
    t.a1b = 0; t.a1e = 0; t.a2b = 0; t.a2e = 0; t.A1 = ufe; t.A2 = ufe;
    t.B = Wpu + 64 * 64; t.bsy = 0; t.gs = nullptr;
    t.out = pfeu; t.ostride = 64; t.osy = 0;
    t.M = NFEAT; t.K = 64; t.scale = 0.1f;
    pgemm<<<dim3((NFEAT + 127) / 128, 1), 256, SMEM_P>>>(t);

    t.A0 = ife; t.A1 = ife; t.A2 = ife; t.B = Wpi + 64 * 64; t.out = pfei;
    pgemm<<<dim3((NFEAT + 127) / 128, 1), 256, SMEM_P>>>(t);

    t.A0 = wemb; t.A1 = wemb; t.A2 = wemb; t.a0e = 32; t.a0rs = 32;
    t.B = Wpu + 128 * 64; t.bsy = 32 * 64;
    t.out = pwu; t.ostride = 192; t.osy = 64;
    t.M = VOCABC; t.K = 32; t.scale = 0.125f;
    pgemm<<<dim3((VOCABC + 127) / 128, 3), 256, SMEM_P>>>(t);

    t.B = Wpi + 128 * 64; t.out = pwi;
    pgemm<<<dim3((VOCABC + 127) / 128, 3), 256, SMEM_P>>>(t);

    // ---- gather: gs = bias + numeric@Wnum + feat + text ----
    gather_kernel<<<(N_USERC * 32 + 255) / 256, 256>>>(
        ufi, uti, unum, Wnu, bpu, bnu, pfeu, pwu, pgs, N_USERC);
    gather_kernel<<<(M_ITEMC * 32 + 255) / 256, 256>>>(
        ifi, iti, inum, Wni, bpi, bni, pfei, pwi,
        pgs + (size_t)N_USERC * 64, M_ITEMC);

    // ---- stage 1: x = dense(A) @ B + gs ----
    PArgs u{};
    u.A0 = uide; u.a0e = 64;  u.a0rs = 64;
    u.A1 = uw300; u.a1b = 64; u.a1e = 364; u.a1rs = 300;
    u.A2 = uide; u.a2b = 0; u.a2e = 0; u.a2rs = 0;
    u.B = pBu; u.bsy = 0; u.gs = pgs;
    u.out = px; u.ostride = 64; u.osy = 0;
    u.M = N_USERC; u.K = 384; u.scale = 1.f;
    pgemm<<<dim3((N_USERC + 127) / 128, 1), 256, SMEM_P>>>(u);

    PArgs v{};
    v.A0 = iide; v.a0e = 64;  v.a0rs = 64;
    v.A1 = iw300; v.a1b = 64; v.a1e = 364; v.a1rs = 300;
    v.A2 = is768; v.a2b = 368; v.a2e = 1136; v.a2rs = 768;
    v.B = pBi; v.bsy = 0; v.gs = pgs + (size_t)N_USERC * 64;
    v.out = px + (size_t)N_USERC * 64; v.ostride = 64; v.osy = 0;
    v.M = M_ITEMC; v.K = 1152; v.scale = 1.f;
    pgemm<<<dim3((M_ITEMC + 127) / 128, 1), 256, SMEM_P>>>(v);

    // ---- layer 0 (fused mean+agg+concat GEMM), relu ----
    layer_kernel<1><<<(MROWS + 127) / 128, 256, SMEM_L>>>(
        neigh2, neigh1, seeds, Wv, bv, Ww, bw, ph, MROWS, 1);

    // ---- layer 1, no relu, writes output ----
    layer_kernel<0><<<(BSEED + 127) / 128, 256, SMEM_L>>>(
        nullptr, nullptr, nullptr, Wv + 64 * 64, bv + 64,
        Ww + 128 * 64, bw + 64, out, BSEED, 0);
}